// round 3
// baseline (speedup 1.0000x reference)
#include <cuda_runtime.h>
#include <cstdint>

#define N_NODES 50000
#define N_EDGES 800000
#define D 64
#define N_LAYERS 3

// Scratch (allocation-free rule: __device__ globals). float4 arrays => 16B aligned.
__device__ float4 g_buf0[N_NODES * D / 4];
__device__ float4 g_buf1[N_NODES * D / 4];
__device__ float4 g_agg [N_NODES * D / 4];

// ---------------------------------------------------------------------------
// Zero the aggregation buffer (float4 stores)
// ---------------------------------------------------------------------------
__global__ void zero_kernel(float4* __restrict__ p, int n4) {
    int i = blockIdx.x * blockDim.x + threadIdx.x;
    if (i < n4) p[i] = make_float4(0.f, 0.f, 0.f, 0.f);
}

// ---------------------------------------------------------------------------
// Edge scatter: agg[dst] += x[src]   (16 threads per edge, float4 lanes)
// Indices are int32 (JAX default config demotes int64 -> int32).
// ---------------------------------------------------------------------------
__global__ void scatter_kernel(const float4* __restrict__ x4,
                               const int* __restrict__ src,
                               const int* __restrict__ dst,
                               float4* __restrict__ agg4) {
    int gid  = blockIdx.x * blockDim.x + threadIdx.x;
    int eid  = gid >> 4;
    int lane = gid & 15;
    if (eid >= N_EDGES) return;
    int s = src[eid];
    int d = dst[eid];
    float4 v = __ldg(x4 + (size_t)s * (D / 4) + lane);
    atomicAdd(agg4 + (size_t)d * (D / 4) + lane, v);
}

// ---------------------------------------------------------------------------
// Fused node update: out = relu?( x @ Wself + agg @ Wmsg + b )
// 64-row tile per block, 256 threads, W + padded x/agg tiles in dynamic smem.
// ---------------------------------------------------------------------------
#define SMEM_FLOATS (2 * 64 * 64 + 2 * 64 * 65)

__global__ void __launch_bounds__(256) node_gemm_kernel(
        const float* __restrict__ x,
        const float* __restrict__ agg,
        const float* __restrict__ Wself,
        const float* __restrict__ Wmsg,
        const float* __restrict__ bias,
        float* __restrict__ out,
        int apply_relu) {
    extern __shared__ float sm[];
    float* sWs = sm;                    // [64][64]
    float* sWm = sm + 64 * 64;          // [64][64]
    float* sX  = sm + 2 * 64 * 64;      // [64][65] padded
    float* sA  = sX + 64 * 65;          // [64][65] padded

    const int tid     = threadIdx.x;
    const int rowbase = blockIdx.x * 64;

    // Load both 64x64 weight matrices (float4, fully coalesced)
    for (int i = tid; i < 64 * 64 / 4; i += 256) {
        reinterpret_cast<float4*>(sWs)[i] = reinterpret_cast<const float4*>(Wself)[i];
        reinterpret_cast<float4*>(sWm)[i] = reinterpret_cast<const float4*>(Wmsg)[i];
    }
    // Load 64-row x/agg tiles into padded smem
    for (int i = tid; i < 64 * 16; i += 256) {
        int r = i >> 4;        // row in tile
        int c = i & 15;        // float4 index in row
        int grow = rowbase + r;
        float4 vx = make_float4(0.f, 0.f, 0.f, 0.f);
        float4 va = vx;
        if (grow < N_NODES) {
            vx = reinterpret_cast<const float4*>(x   + (size_t)grow * D)[c];
            va = reinterpret_cast<const float4*>(agg + (size_t)grow * D)[c];
        }
        float* dx = sX + r * 65 + c * 4;
        dx[0] = vx.x; dx[1] = vx.y; dx[2] = vx.z; dx[3] = vx.w;
        float* da = sA + r * 65 + c * 4;
        da[0] = va.x; da[1] = va.y; da[2] = va.z; da[3] = va.w;
    }
    __syncthreads();

    // thread -> (row, 16-col group)
    const int r  = tid >> 2;
    const int c0 = (tid & 3) * 16;

    float acc[16];
    #pragma unroll
    for (int j = 0; j < 16; j++) acc[j] = bias[c0 + j];

    #pragma unroll 8
    for (int k = 0; k < 64; k++) {
        float xv = sX[r * 65 + k];
        float av = sA[r * 65 + k];
        #pragma unroll
        for (int j = 0; j < 16; j += 4) {
            float4 ws = *reinterpret_cast<const float4*>(sWs + k * 64 + c0 + j);
            float4 wm = *reinterpret_cast<const float4*>(sWm + k * 64 + c0 + j);
            acc[j + 0] += xv * ws.x + av * wm.x;
            acc[j + 1] += xv * ws.y + av * wm.y;
            acc[j + 2] += xv * ws.z + av * wm.z;
            acc[j + 3] += xv * ws.w + av * wm.w;
        }
    }

    const int grow = rowbase + r;
    if (grow < N_NODES) {
        float* op = out + (size_t)grow * D + c0;
        #pragma unroll
        for (int j = 0; j < 16; j += 4) {
            float4 v;
            v.x = acc[j + 0]; v.y = acc[j + 1]; v.z = acc[j + 2]; v.w = acc[j + 3];
            if (apply_relu) {
                v.x = fmaxf(v.x, 0.f); v.y = fmaxf(v.y, 0.f);
                v.z = fmaxf(v.z, 0.f); v.w = fmaxf(v.w, 0.f);
            }
            *reinterpret_cast<float4*>(op + j) = v;
        }
    }
}

// ---------------------------------------------------------------------------
// Launch
// ---------------------------------------------------------------------------
extern "C" void kernel_launch(void* const* d_in, const int* in_sizes, int n_in,
                              void* d_out, int out_size) {
    (void)in_sizes; (void)n_in; (void)out_size;

    const float* x0    = (const float*)d_in[0];
    const int*   ei    = (const int*)d_in[1];      // int32 (JAX x64 disabled)
    const float* Wmsg  = (const float*)d_in[2];    // [3][64][64]
    const float* Wself = (const float*)d_in[3];    // [3][64][64]
    const float* bias  = (const float*)d_in[4];    // [3][64]
    float*       out   = (float*)d_out;

    const int* src = ei;
    const int* dst = ei + N_EDGES;

    float4 *buf0, *buf1, *agg;
    cudaGetSymbolAddress((void**)&buf0, g_buf0);
    cudaGetSymbolAddress((void**)&buf1, g_buf1);
    cudaGetSymbolAddress((void**)&agg,  g_agg);

    static bool attr_set = false;
    const int smem_bytes = SMEM_FLOATS * (int)sizeof(float);
    if (!attr_set) {
        cudaFuncSetAttribute(node_gemm_kernel,
                             cudaFuncAttributeMaxDynamicSharedMemorySize, smem_bytes);
        attr_set = true;
    }

    const float* cur[N_LAYERS]  = { x0, (const float*)buf0, (const float*)buf1 };
    float*       next[N_LAYERS] = { (float*)buf0, (float*)buf1, out };

    const int n4          = N_NODES * D / 4;
    const int zero_blocks = (n4 + 255) / 256;
    const int scat_blocks = (N_EDGES * 16 + 255) / 256;
    const int gemm_blocks = (N_NODES + 63) / 64;

    for (int layer = 0; layer < N_LAYERS; layer++) {
        zero_kernel<<<zero_blocks, 256>>>(agg, n4);
        scatter_kernel<<<scat_blocks, 256>>>(
            (const float4*)cur[layer], src, dst, agg);
        node_gemm_kernel<<<gemm_blocks, 256, smem_bytes>>>(
            cur[layer], (const float*)agg,
            Wself + (size_t)layer * D * D,
            Wmsg  + (size_t)layer * D * D,
            bias  + (size_t)layer * D,
            next[layer],
            layer < N_LAYERS - 1 ? 1 : 0);
    }
}